// round 16
// baseline (speedup 1.0000x reference)
#include <cuda_runtime.h>
#include <cuda_fp16.h>
#include <math_constants.h>
#include <cstdint>

// Attention B=256,H=16,Nq=Nk=49,D=64 fp32. One CTA (128 thr, 4 warps) per TWO
// (b,h) heads. R16 = R15 compute (single-term fp16 MMAs, fp32 accum, scalar
// key-48, log2 softmax) with both heads' K/V loaded up front -> ONE barrier
// and one DRAM-latency exposure per 2 heads. Smem 27.6KB, 8 CTAs/SM.

namespace {
constexpr int kNQ = 49, kNK = 49, kD = 64;
constexpr int kP  = 72;                     // fp16 pitch (144B = 9*16)
constexpr float kQscale = 0.125f * 1.4426950408889634f;  // scale * log2(e)
constexpr float kEps    = 1e-9f;
constexpr int kROWB = 144;
constexpr int kARR  = 48 * kROWB;               // 6912
constexpr int kHEADSM = 2 * kARR;               // K+V per head = 13824
constexpr int SMEM_BYTES = 2 * kHEADSM;         // 27648
constexpr int kHE = kNQ * kD;                   // elements per head
}

__device__ __forceinline__ uint32_t cvta_s(const void* p) {
    return (uint32_t)__cvta_generic_to_shared(p);
}
__device__ __forceinline__ void ldsm4(uint32_t& r0, uint32_t& r1, uint32_t& r2, uint32_t& r3, uint32_t a) {
    asm volatile("ldmatrix.sync.aligned.m8n8.x4.shared.b16 {%0,%1,%2,%3}, [%4];\n"
                 : "=r"(r0), "=r"(r1), "=r"(r2), "=r"(r3) : "r"(a));
}
__device__ __forceinline__ void ldsm4t(uint32_t& r0, uint32_t& r1, uint32_t& r2, uint32_t& r3, uint32_t a) {
    asm volatile("ldmatrix.sync.aligned.m8n8.x4.trans.shared.b16 {%0,%1,%2,%3}, [%4];\n"
                 : "=r"(r0), "=r"(r1), "=r"(r2), "=r"(r3) : "r"(a));
}
__device__ __forceinline__ void mma16816(float* c,
                                         uint32_t a0, uint32_t a1, uint32_t a2, uint32_t a3,
                                         uint32_t b0, uint32_t b1) {
    asm volatile("mma.sync.aligned.m16n8k16.row.col.f32.f16.f16.f32 "
                 "{%0,%1,%2,%3}, {%4,%5,%6,%7}, {%8,%9}, {%0,%1,%2,%3};\n"
                 : "+f"(c[0]), "+f"(c[1]), "+f"(c[2]), "+f"(c[3])
                 : "r"(a0), "r"(a1), "r"(a2), "r"(a3), "r"(b0), "r"(b1));
}
__device__ __forceinline__ uint32_t packh2(float lo, float hi) {
    uint32_t r;
    asm("cvt.rn.f16x2.f32 %0, %1, %2;" : "=r"(r) : "f"(hi), "f"(lo));
    return r;
}

__global__ __launch_bounds__(128, 8)
void attn49_v16(const float* __restrict__ gq,
                const float* __restrict__ gk,
                const float* __restrict__ gv,
                float* __restrict__ gout)
{
    __shared__ __align__(16) char sraw[SMEM_BYTES];

    const int tid  = threadIdx.x;
    const int w    = tid >> 5;
    const int lane = tid & 31;
    const int g    = lane >> 3;
    const int lr   = lane & 7;

    const size_t pbase = (size_t)blockIdx.x * (2 * kHE);   // head pair base

    const int qtb = w * 16;
    const int q0 = qtb + (lane >> 2);
    const int q1 = q0 + 8;
    const bool p0 = q0 < kNQ;
    const bool p1 = q1 < kNQ;
    const int cq = 2 * (lane & 3);

    // ---- Load K/V rows 0-47 for BOTH heads (single fp16), front-batched ----
    {
        const float4* K4a = (const float4*)(gk + pbase);
        const float4* V4a = (const float4*)(gv + pbase);
        const float4* K4b = (const float4*)(gk + pbase + kHE);
        const float4* V4b = (const float4*)(gv + pbase + kHE);
        for (int idx = tid; idx < 48 * 16; idx += 128) {
            const int r = idx >> 4, c4 = idx & 15;
            const float4 ka = K4a[idx];
            const float4 va = V4a[idx];
            const float4 kb = K4b[idx];
            const float4 vb = V4b[idx];
            const int ro = r * kROWB + c4 * 8;
            *(uint2*)(sraw + ro)                 = make_uint2(packh2(ka.x, ka.y), packh2(ka.z, ka.w));
            *(uint2*)(sraw + kARR + ro)          = make_uint2(packh2(va.x, va.y), packh2(va.z, va.w));
            *(uint2*)(sraw + kHEADSM + ro)       = make_uint2(packh2(kb.x, kb.y), packh2(kb.z, kb.w));
            *(uint2*)(sraw + kHEADSM + kARR + ro)= make_uint2(packh2(vb.x, vb.y), packh2(vb.z, vb.w));
        }
    }
    __syncthreads();   // the ONLY barrier (per 2 heads)

    for (int h = 0; h < 2; h++) {
        const size_t base = pbase + (size_t)h * kHE;
        const float2* Q2  = (const float2*)(gq + base);
        const float2* K48 = (const float2*)(gk + base + 48 * kD);
        const float2* V48 = (const float2*)(gv + base + 48 * kD);
        float* O = gout + base;
        const uint32_t aKh = cvta_s(sraw + h * kHEADSM);
        const uint32_t aVh = aKh + kARR;

        // ---- Phase 1: S[16q][48k] = Q_h.K_h; s48 scalar fp32 alongside ----
        float acc[6][4];
        #pragma unroll
        for (int i = 0; i < 6; i++)
            #pragma unroll
            for (int j = 0; j < 4; j++) acc[i][j] = 0.0f;
        float s48_0 = 0.0f, s48_1 = 0.0f;
        {
            const int ro = lr + ((g & 1) << 3);
            const int co = (g >> 1) << 3;
            #pragma unroll
            for (int kc = 0; kc < 4; kc++) {
                uint32_t ah[4];
                {
                    const int cb = kc * 8 + (lane & 3);
                    float2 x0 = p0 ? Q2[q0 * 32 + cb]     : make_float2(0.f, 0.f);
                    float2 x1 = p1 ? Q2[q1 * 32 + cb]     : make_float2(0.f, 0.f);
                    float2 x2 = p0 ? Q2[q0 * 32 + cb + 4] : make_float2(0.f, 0.f);
                    float2 x3 = p1 ? Q2[q1 * 32 + cb + 4] : make_float2(0.f, 0.f);
                    x0.x *= kQscale; x0.y *= kQscale; x1.x *= kQscale; x1.y *= kQscale;
                    x2.x *= kQscale; x2.y *= kQscale; x3.x *= kQscale; x3.y *= kQscale;
                    ah[0] = packh2(x0.x, x0.y);
                    ah[1] = packh2(x1.x, x1.y);
                    ah[2] = packh2(x2.x, x2.y);
                    ah[3] = packh2(x3.x, x3.y);
                    const float2 ka = K48[cb];
                    const float2 kb = K48[cb + 4];
                    s48_0 = fmaf(x0.x, ka.x, fmaf(x0.y, ka.y,
                            fmaf(x2.x, kb.x, fmaf(x2.y, kb.y, s48_0))));
                    s48_1 = fmaf(x1.x, ka.x, fmaf(x1.y, ka.y,
                            fmaf(x3.x, kb.x, fmaf(x3.y, kb.y, s48_1))));
                }
                const int d = kc * 16;
                {
                    const int b0 = ro * kP + d + co;
                    const int b1 = (16 + ro) * kP + d + co;
                    uint32_t xh0, xh1, xh2, xh3;
                    uint32_t yh0, yh1, yh2, yh3;
                    ldsm4(xh0, xh1, xh2, xh3, aKh + b0 * 2);
                    ldsm4(yh0, yh1, yh2, yh3, aKh + b1 * 2);
                    mma16816(acc[0], ah[0], ah[1], ah[2], ah[3], xh0, xh2);
                    mma16816(acc[1], ah[0], ah[1], ah[2], ah[3], xh1, xh3);
                    mma16816(acc[2], ah[0], ah[1], ah[2], ah[3], yh0, yh2);
                    mma16816(acc[3], ah[0], ah[1], ah[2], ah[3], yh1, yh3);
                }
                {
                    const int b2 = (32 + ro) * kP + d + co;
                    uint32_t zh0, zh1, zh2, zh3;
                    ldsm4(zh0, zh1, zh2, zh3, aKh + b2 * 2);
                    mma16816(acc[4], ah[0], ah[1], ah[2], ah[3], zh0, zh2);
                    mma16816(acc[5], ah[0], ah[1], ah[2], ah[3], zh1, zh3);
                }
            }
            s48_0 += __shfl_xor_sync(0xffffffffu, s48_0, 1);
            s48_0 += __shfl_xor_sync(0xffffffffu, s48_0, 2);
            s48_1 += __shfl_xor_sync(0xffffffffu, s48_1, 1);
            s48_1 += __shfl_xor_sync(0xffffffffu, s48_1, 2);
        }

        // ---- Register softmax, log2 domain ----
        float m0 = s48_0, m1 = s48_1;
        #pragma unroll
        for (int nt = 0; nt < 6; nt++) {
            m0 = fmaxf(m0, fmaxf(acc[nt][0], acc[nt][1]));
            m1 = fmaxf(m1, fmaxf(acc[nt][2], acc[nt][3]));
        }
        m0 = fmaxf(m0, __shfl_xor_sync(0xffffffffu, m0, 1));
        m0 = fmaxf(m0, __shfl_xor_sync(0xffffffffu, m0, 2));
        m1 = fmaxf(m1, __shfl_xor_sync(0xffffffffu, m1, 1));
        m1 = fmaxf(m1, __shfl_xor_sync(0xffffffffu, m1, 2));

        float l0 = 0.0f, l1 = 0.0f;
        #pragma unroll
        for (int nt = 0; nt < 6; nt++) {
            const float e0 = exp2f(acc[nt][0] - m0);
            const float e1 = exp2f(acc[nt][1] - m0);
            const float e2 = exp2f(acc[nt][2] - m1);
            const float e3 = exp2f(acc[nt][3] - m1);
            acc[nt][0] = e0; acc[nt][1] = e1; acc[nt][2] = e2; acc[nt][3] = e3;
            l0 += e0 + e1; l1 += e2 + e3;
        }
        l0 += __shfl_xor_sync(0xffffffffu, l0, 1);
        l0 += __shfl_xor_sync(0xffffffffu, l0, 2);
        l1 += __shfl_xor_sync(0xffffffffu, l1, 1);
        l1 += __shfl_xor_sync(0xffffffffu, l1, 2);

        const float p48_0 = exp2f(s48_0 - m0);
        const float p48_1 = exp2f(s48_1 - m1);
        const float linv0 = 1.0f / (l0 + p48_0 + kEps);
        const float linv1 = 1.0f / (l1 + p48_1 + kEps);

        // ---- Repack P (cols 0-47) as single-fp16 A-fragments ----
        uint32_t aP[3][4];
        #pragma unroll
        for (int kc = 0; kc < 3; kc++) {
            #pragma unroll
            for (int t = 0; t < 2; t++) {
                aP[kc][2 * t]     = packh2(acc[2 * kc + t][0], acc[2 * kc + t][1]);
                aP[kc][2 * t + 1] = packh2(acc[2 * kc + t][2], acc[2 * kc + t][3]);
            }
        }

        // ---- Phase 2: O = P_h.V_h over k 0-47 + p48*V[48] (scalar fp32) ----
        #pragma unroll
        for (int half = 0; half < 2; half++) {
            const int db = half * 32;
            float2 vv[4];
            #pragma unroll
            for (int nt = 0; nt < 4; nt++)
                vv[nt] = V48[(db >> 1) + nt * 4 + (cq >> 1)];

            float o[4][4];
            #pragma unroll
            for (int i = 0; i < 4; i++)
                #pragma unroll
                for (int j = 0; j < 4; j++) o[i][j] = 0.0f;

            #pragma unroll
            for (int kc = 0; kc < 3; kc++) {
                const int kk = kc * 16;
                const int bo0 = (kk + ((g >> 1) << 3) + lr) * kP + db      + ((g & 1) << 3);
                const int bo1 = (kk + ((g >> 1) << 3) + lr) * kP + db + 16 + ((g & 1) << 3);
                uint32_t xh0, xh1, xh2, xh3;
                uint32_t yh0, yh1, yh2, yh3;
                ldsm4t(xh0, xh1, xh2, xh3, aVh + bo0 * 2);
                ldsm4t(yh0, yh1, yh2, yh3, aVh + bo1 * 2);
                mma16816(o[0], aP[kc][0], aP[kc][1], aP[kc][2], aP[kc][3], xh0, xh2);
                mma16816(o[1], aP[kc][0], aP[kc][1], aP[kc][2], aP[kc][3], xh1, xh3);
                mma16816(o[2], aP[kc][0], aP[kc][1], aP[kc][2], aP[kc][3], yh0, yh2);
                mma16816(o[3], aP[kc][0], aP[kc][1], aP[kc][2], aP[kc][3], yh1, yh3);
            }

            #pragma unroll
            for (int nt = 0; nt < 4; nt++) {
                const int d = db + nt * 8 + cq;
                if (p0)
                    *(float2*)(O + q0 * kD + d) =
                        make_float2((o[nt][0] + p48_0 * vv[nt].x) * linv0,
                                    (o[nt][1] + p48_0 * vv[nt].y) * linv0);
                if (p1)
                    *(float2*)(O + q1 * kD + d) =
                        make_float2((o[nt][2] + p48_1 * vv[nt].x) * linv1,
                                    (o[nt][3] + p48_1 * vv[nt].y) * linv1);
            }
        }
    }
}

extern "C" void kernel_launch(void* const* d_in, const int* in_sizes, int n_in,
                              void* d_out, int out_size)
{
    const float* q = (const float*)d_in[0];
    const float* k = (const float*)d_in[1];
    const float* v = (const float*)d_in[2];
    float* out = (float*)d_out;

    const int pairs = in_sizes[0] / (2 * kNQ * kD);   // 2048
    attn49_v16<<<pairs, 128>>>(q, k, v, out);
}

// round 17
// speedup vs baseline: 1.1231x; 1.1231x over previous
#include <cuda_runtime.h>
#include <cuda_fp16.h>
#include <math_constants.h>
#include <cstdint>

// Attention B=256,H=16,Nq=Nk=49,D=64 fp32. One CTA (128 thr, 4 warps) per (b,h).
// R17 = R15 compute (single-term fp16 MMAs, fp32 accum, scalar key-48, log2
// softmax) with ALL gmem loads front-batched BEFORE the single barrier:
// Q -> fp16 A-fragments in registers, s48 computed pre-barrier (no smem dep),
// K/V cooperative fp16 stores. Post-barrier compute touches gmem only for the
// hoisted V48 prefetch and output stores. Smem 13.8KB, launch_bounds(128,8).

namespace {
constexpr int kNQ = 49, kNK = 49, kD = 64;
constexpr int kP  = 72;                     // fp16 pitch (144B = 9*16)
constexpr float kQscale = 0.125f * 1.4426950408889634f;  // scale * log2(e)
constexpr float kEps    = 1e-9f;
constexpr int kROWB = 144;
constexpr int OFF_KH = 0;
constexpr int OFF_VH = 48 * kROWB;              // 6912
constexpr int SMEM_BYTES = OFF_VH + 48 * kROWB; // 13824
}

__device__ __forceinline__ uint32_t cvta_s(const void* p) {
    return (uint32_t)__cvta_generic_to_shared(p);
}
__device__ __forceinline__ void ldsm4(uint32_t& r0, uint32_t& r1, uint32_t& r2, uint32_t& r3, uint32_t a) {
    asm volatile("ldmatrix.sync.aligned.m8n8.x4.shared.b16 {%0,%1,%2,%3}, [%4];\n"
                 : "=r"(r0), "=r"(r1), "=r"(r2), "=r"(r3) : "r"(a));
}
__device__ __forceinline__ void ldsm4t(uint32_t& r0, uint32_t& r1, uint32_t& r2, uint32_t& r3, uint32_t a) {
    asm volatile("ldmatrix.sync.aligned.m8n8.x4.trans.shared.b16 {%0,%1,%2,%3}, [%4];\n"
                 : "=r"(r0), "=r"(r1), "=r"(r2), "=r"(r3) : "r"(a));
}
__device__ __forceinline__ void mma16816(float* c,
                                         uint32_t a0, uint32_t a1, uint32_t a2, uint32_t a3,
                                         uint32_t b0, uint32_t b1) {
    asm volatile("mma.sync.aligned.m16n8k16.row.col.f32.f16.f16.f32 "
                 "{%0,%1,%2,%3}, {%4,%5,%6,%7}, {%8,%9}, {%0,%1,%2,%3};\n"
                 : "+f"(c[0]), "+f"(c[1]), "+f"(c[2]), "+f"(c[3])
                 : "r"(a0), "r"(a1), "r"(a2), "r"(a3), "r"(b0), "r"(b1));
}
__device__ __forceinline__ uint32_t packh2(float lo, float hi) {
    uint32_t r;
    asm("cvt.rn.f16x2.f32 %0, %1, %2;" : "=r"(r) : "f"(hi), "f"(lo));
    return r;
}

__global__ __launch_bounds__(128, 8)
void attn49_v17(const float* __restrict__ gq,
                const float* __restrict__ gk,
                const float* __restrict__ gv,
                float* __restrict__ gout)
{
    __shared__ __align__(16) char sraw[SMEM_BYTES];

    const int tid  = threadIdx.x;
    const int w    = tid >> 5;
    const int lane = tid & 31;
    const int g    = lane >> 3;
    const int lr   = lane & 7;

    const size_t base = (size_t)blockIdx.x * (kNQ * kD);
    const float2* Q2  = (const float2*)(gq + base);
    const float4* K4  = (const float4*)(gk + base);
    const float4* V4  = (const float4*)(gv + base);
    const float2* K48 = (const float2*)(gk + base + 48 * kD);
    const float2* V48 = (const float2*)(gv + base + 48 * kD);
    float* O = gout + base;

    const int qtb = w * 16;
    const int q0 = qtb + (lane >> 2);
    const int q1 = q0 + 8;
    const bool p0 = q0 < kNQ;
    const bool p1 = q1 < kNQ;
    const int cq = 2 * (lane & 3);

    // ================= PRE-BARRIER: ALL gmem loads =================
    // (a) Q -> fp16 A-fragments in registers; s48 partials from K48 (gmem only)
    uint32_t qA[4][4];
    float s48_0 = 0.0f, s48_1 = 0.0f;
    #pragma unroll
    for (int kc = 0; kc < 4; kc++) {
        const int cb = kc * 8 + (lane & 3);
        float2 x0 = p0 ? Q2[q0 * 32 + cb]     : make_float2(0.f, 0.f);
        float2 x1 = p1 ? Q2[q1 * 32 + cb]     : make_float2(0.f, 0.f);
        float2 x2 = p0 ? Q2[q0 * 32 + cb + 4] : make_float2(0.f, 0.f);
        float2 x3 = p1 ? Q2[q1 * 32 + cb + 4] : make_float2(0.f, 0.f);
        const float2 ka = K48[cb];
        const float2 kb = K48[cb + 4];
        x0.x *= kQscale; x0.y *= kQscale; x1.x *= kQscale; x1.y *= kQscale;
        x2.x *= kQscale; x2.y *= kQscale; x3.x *= kQscale; x3.y *= kQscale;
        qA[kc][0] = packh2(x0.x, x0.y);
        qA[kc][1] = packh2(x1.x, x1.y);
        qA[kc][2] = packh2(x2.x, x2.y);
        qA[kc][3] = packh2(x3.x, x3.y);
        s48_0 = fmaf(x0.x, ka.x, fmaf(x0.y, ka.y,
                fmaf(x2.x, kb.x, fmaf(x2.y, kb.y, s48_0))));
        s48_1 = fmaf(x1.x, ka.x, fmaf(x1.y, ka.y,
                fmaf(x3.x, kb.x, fmaf(x3.y, kb.y, s48_1))));
    }
    // (b) cooperative K/V rows 0-47 -> smem fp16
    for (int idx = tid; idx < 48 * 16; idx += 128) {
        const int r = idx >> 4, c4 = idx & 15;
        const float4 k = K4[idx];
        const float4 v = V4[idx];
        const int ro = r * kROWB + c4 * 8;
        *(uint2*)(sraw + OFF_KH + ro) =
            make_uint2(packh2(k.x, k.y), packh2(k.z, k.w));
        *(uint2*)(sraw + OFF_VH + ro) =
            make_uint2(packh2(v.x, v.y), packh2(v.z, v.w));
    }
    // complete s48 across the quad (pre-barrier; register-only)
    s48_0 += __shfl_xor_sync(0xffffffffu, s48_0, 1);
    s48_0 += __shfl_xor_sync(0xffffffffu, s48_0, 2);
    s48_1 += __shfl_xor_sync(0xffffffffu, s48_1, 1);
    s48_1 += __shfl_xor_sync(0xffffffffu, s48_1, 2);
    __syncthreads();   // the ONLY barrier

    // ================= Phase 1: S[16q][48k] = Q_h.K_h (no LDG) =================
    float acc[6][4];
    #pragma unroll
    for (int i = 0; i < 6; i++)
        #pragma unroll
        for (int j = 0; j < 4; j++) acc[i][j] = 0.0f;
    {
        const uint32_t aKh = cvta_s(sraw + OFF_KH);
        const int ro = lr + ((g & 1) << 3);
        const int co = (g >> 1) << 3;
        #pragma unroll
        for (int kc = 0; kc < 4; kc++) {
            const int d = kc * 16;
            {
                const int b0 = ro * kP + d + co;
                const int b1 = (16 + ro) * kP + d + co;
                uint32_t xh0, xh1, xh2, xh3;
                uint32_t yh0, yh1, yh2, yh3;
                ldsm4(xh0, xh1, xh2, xh3, aKh + b0 * 2);
                ldsm4(yh0, yh1, yh2, yh3, aKh + b1 * 2);
                mma16816(acc[0], qA[kc][0], qA[kc][1], qA[kc][2], qA[kc][3], xh0, xh2);
                mma16816(acc[1], qA[kc][0], qA[kc][1], qA[kc][2], qA[kc][3], xh1, xh3);
                mma16816(acc[2], qA[kc][0], qA[kc][1], qA[kc][2], qA[kc][3], yh0, yh2);
                mma16816(acc[3], qA[kc][0], qA[kc][1], qA[kc][2], qA[kc][3], yh1, yh3);
            }
            {
                const int b2 = (32 + ro) * kP + d + co;
                uint32_t zh0, zh1, zh2, zh3;
                ldsm4(zh0, zh1, zh2, zh3, aKh + b2 * 2);
                mma16816(acc[4], qA[kc][0], qA[kc][1], qA[kc][2], qA[kc][3], zh0, zh2);
                mma16816(acc[5], qA[kc][0], qA[kc][1], qA[kc][2], qA[kc][3], zh1, zh3);
            }
        }
    }

    // ================= Register softmax, log2 domain =================
    float m0 = s48_0, m1 = s48_1;
    #pragma unroll
    for (int nt = 0; nt < 6; nt++) {
        m0 = fmaxf(m0, fmaxf(acc[nt][0], acc[nt][1]));
        m1 = fmaxf(m1, fmaxf(acc[nt][2], acc[nt][3]));
    }
    m0 = fmaxf(m0, __shfl_xor_sync(0xffffffffu, m0, 1));
    m0 = fmaxf(m0, __shfl_xor_sync(0xffffffffu, m0, 2));
    m1 = fmaxf(m1, __shfl_xor_sync(0xffffffffu, m1, 1));
    m1 = fmaxf(m1, __shfl_xor_sync(0xffffffffu, m1, 2));

    // hoisted V48 prefetch for BOTH phase-2 halves (only post-barrier LDGs)
    float2 vv[2][4];
    #pragma unroll
    for (int half = 0; half < 2; half++)
        #pragma unroll
        for (int nt = 0; nt < 4; nt++)
            vv[half][nt] = V48[half * 16 + nt * 4 + (cq >> 1)];

    float l0 = 0.0f, l1 = 0.0f;
    #pragma unroll
    for (int nt = 0; nt < 6; nt++) {
        const float e0 = exp2f(acc[nt][0] - m0);
        const float e1 = exp2f(acc[nt][1] - m0);
        const float e2 = exp2f(acc[nt][2] - m1);
        const float e3 = exp2f(acc[nt][3] - m1);
        acc[nt][0] = e0; acc[nt][1] = e1; acc[nt][2] = e2; acc[nt][3] = e3;
        l0 += e0 + e1; l1 += e2 + e3;
    }
    l0 += __shfl_xor_sync(0xffffffffu, l0, 1);
    l0 += __shfl_xor_sync(0xffffffffu, l0, 2);
    l1 += __shfl_xor_sync(0xffffffffu, l1, 1);
    l1 += __shfl_xor_sync(0xffffffffu, l1, 2);

    const float p48_0 = exp2f(s48_0 - m0);
    const float p48_1 = exp2f(s48_1 - m1);
    const float linv0 = 1.0f / (l0 + p48_0 + kEps);
    const float linv1 = 1.0f / (l1 + p48_1 + kEps);

    // ---- Repack P (cols 0-47) as single-fp16 A-fragments ----
    uint32_t aP[3][4];
    #pragma unroll
    for (int kc = 0; kc < 3; kc++) {
        #pragma unroll
        for (int t = 0; t < 2; t++) {
            aP[kc][2 * t]     = packh2(acc[2 * kc + t][0], acc[2 * kc + t][1]);
            aP[kc][2 * t + 1] = packh2(acc[2 * kc + t][2], acc[2 * kc + t][3]);
        }
    }

    // ================= Phase 2: O = P_h.V_h + p48*V[48] =================
    const uint32_t aVh = cvta_s(sraw + OFF_VH);
    #pragma unroll
    for (int half = 0; half < 2; half++) {
        const int db = half * 32;
        float o[4][4];
        #pragma unroll
        for (int i = 0; i < 4; i++)
            #pragma unroll
            for (int j = 0; j < 4; j++) o[i][j] = 0.0f;

        #pragma unroll
        for (int kc = 0; kc < 3; kc++) {
            const int kk = kc * 16;
            const int bo0 = (kk + ((g >> 1) << 3) + lr) * kP + db      + ((g & 1) << 3);
            const int bo1 = (kk + ((g >> 1) << 3) + lr) * kP + db + 16 + ((g & 1) << 3);
            uint32_t xh0, xh1, xh2, xh3;
            uint32_t yh0, yh1, yh2, yh3;
            ldsm4t(xh0, xh1, xh2, xh3, aVh + bo0 * 2);
            ldsm4t(yh0, yh1, yh2, yh3, aVh + bo1 * 2);
            mma16816(o[0], aP[kc][0], aP[kc][1], aP[kc][2], aP[kc][3], xh0, xh2);
            mma16816(o[1], aP[kc][0], aP[kc][1], aP[kc][2], aP[kc][3], xh1, xh3);
            mma16816(o[2], aP[kc][0], aP[kc][1], aP[kc][2], aP[kc][3], yh0, yh2);
            mma16816(o[3], aP[kc][0], aP[kc][1], aP[kc][2], aP[kc][3], yh1, yh3);
        }

        #pragma unroll
        for (int nt = 0; nt < 4; nt++) {
            const int d = db + nt * 8 + cq;
            if (p0)
                *(float2*)(O + q0 * kD + d) =
                    make_float2((o[nt][0] + p48_0 * vv[half][nt].x) * linv0,
                                (o[nt][1] + p48_0 * vv[half][nt].y) * linv0);
            if (p1)
                *(float2*)(O + q1 * kD + d) =
                    make_float2((o[nt][2] + p48_1 * vv[half][nt].x) * linv1,
                                (o[nt][3] + p48_1 * vv[half][nt].y) * linv1);
        }
    }
}

extern "C" void kernel_launch(void* const* d_in, const int* in_sizes, int n_in,
                              void* d_out, int out_size)
{
    const float* q = (const float*)d_in[0];
    const float* k = (const float*)d_in[1];
    const float* v = (const float*)d_in[2];
    float* out = (float*)d_out;

    const int bh = in_sizes[0] / (kNQ * kD);   // 4096
    attn49_v17<<<bh, 128>>>(q, k, v, out);
}